// round 1
// baseline (speedup 1.0000x reference)
#include <cuda_runtime.h>
#include <math.h>

// ---------------- problem constants ----------------
#define B_      1024
#define NTOK    54          // 49 window + 5 prompt tokens
#define WIN     49
#define NP      5
#define NH      12
#define HD      32
#define DIM     384         // NH*HD
#define QKVD    1152        // 3*DIM
#define NWIN    64
#define WH      7
#define WW      7
#define SCALE   0.17677669529663687f   // 1/sqrt(32)

#define MTOK    (B_*NTOK)   // 55296

// ---------------- scratch (device globals; no runtime alloc) ----------------
__device__ float d_qkv[(size_t)MTOK * QKVD];   // 55296 x 1152
__device__ float d_att[(size_t)MTOK * DIM];    // 55296 x 384 (pre-proj)
__device__ float d_bias[NH * NTOK * NTOK];     // padded rel-pos bias

// ---------------- bias precompute ----------------
__global__ void bias_kernel(const float* __restrict__ rpb) {
    int idx = blockIdx.x * blockDim.x + threadIdx.x;
    const int total = NH * NTOK * NTOK;
    if (idx >= total) return;
    int h  = idx / (NTOK * NTOK);
    int r  = idx % (NTOK * NTOK);
    int qi = r / NTOK, kj = r % NTOK;
    float v = 0.f;
    if (qi >= NP && kj >= NP) {
        int i = qi - NP, j = kj - NP;
        int ih = i / WW, iw = i % WW;
        int jh = j / WW, jw = j % WW;
        int rpi = (ih - jh + WH - 1) * (2 * WW - 1) + (iw - jw + WW - 1);
        v = rpb[rpi * NH + h];
    }
    d_bias[idx] = v;
}

// ---------------- classic 128x128x8 SGEMM: C[M,N] = A[M,K] @ W[N,K]^T + bias ----
// All of M%128, N%128, K%8 are zero for our shapes -> no bounds checks.
__device__ __forceinline__ void sgemm_body(
    const float* __restrict__ A, const float* __restrict__ W,
    const float* __restrict__ bias, float* __restrict__ C,
    int K, int N)
{
    __shared__ float As[8][128];
    __shared__ float Ws[8][128];

    const int tid = threadIdx.x;        // 0..255
    const int tx  = tid & 15;           // 16 col groups
    const int ty  = tid >> 4;           // 16 row groups
    const int m0  = blockIdx.y * 128;
    const int n0  = blockIdx.x * 128;

    const int lr = tid >> 1;            // 0..127 (tile row)
    const int lc = (tid & 1) * 4;       // 0 or 4 (k offset)

    const float* Ap = A + (size_t)(m0 + lr) * K + lc;
    const float* Wp = W + (size_t)(n0 + lr) * K + lc;

    float acc[8][8];
    #pragma unroll
    for (int i = 0; i < 8; i++)
        #pragma unroll
        for (int j = 0; j < 8; j++) acc[i][j] = 0.f;

    for (int k0 = 0; k0 < K; k0 += 8) {
        float4 a = *reinterpret_cast<const float4*>(Ap + k0);
        float4 w = *reinterpret_cast<const float4*>(Wp + k0);
        __syncthreads();
        As[lc + 0][lr] = a.x; As[lc + 1][lr] = a.y;
        As[lc + 2][lr] = a.z; As[lc + 3][lr] = a.w;
        Ws[lc + 0][lr] = w.x; Ws[lc + 1][lr] = w.y;
        Ws[lc + 2][lr] = w.z; Ws[lc + 3][lr] = w.w;
        __syncthreads();

        #pragma unroll
        for (int k = 0; k < 8; k++) {
            float ra[8], rb[8];
            #pragma unroll
            for (int i = 0; i < 8; i++) ra[i] = As[k][ty * 8 + i];
            #pragma unroll
            for (int j = 0; j < 8; j++) rb[j] = Ws[k][tx * 8 + j];
            #pragma unroll
            for (int i = 0; i < 8; i++)
                #pragma unroll
                for (int j = 0; j < 8; j++) acc[i][j] += ra[i] * rb[j];
        }
    }

    const int col = n0 + tx * 8;
    float bv[8];
    #pragma unroll
    for (int j = 0; j < 8; j++) bv[j] = bias[col + j];

    #pragma unroll
    for (int i = 0; i < 8; i++) {
        float* cp = C + (size_t)(m0 + ty * 8 + i) * N + col;
        float4 r0, r1;
        r0.x = acc[i][0] + bv[0]; r0.y = acc[i][1] + bv[1];
        r0.z = acc[i][2] + bv[2]; r0.w = acc[i][3] + bv[3];
        r1.x = acc[i][4] + bv[4]; r1.y = acc[i][5] + bv[5];
        r1.z = acc[i][6] + bv[6]; r1.w = acc[i][7] + bv[7];
        *reinterpret_cast<float4*>(cp)     = r0;
        *reinterpret_cast<float4*>(cp + 4) = r1;
    }
}

__global__ __launch_bounds__(256) void k_qkv(
    const float* __restrict__ x, const float* __restrict__ W,
    const float* __restrict__ b)
{
    sgemm_body(x, W, b, d_qkv, DIM, QKVD);
}

__global__ __launch_bounds__(256) void k_proj(
    const float* __restrict__ W, const float* __restrict__ b,
    float* __restrict__ out)
{
    sgemm_body(d_att, W, b, out, DIM, DIM);
}

// ---------------- fused attention: one block per (b, h) ----------------
__global__ __launch_bounds__(256) void attn_kernel(const float* __restrict__ mask)
{
    __shared__ float qs[NTOK][HD];       // q * SCALE
    __shared__ float ks[64][HD + 1];     // padded rows 54..63 zeroed
    __shared__ float vs[64][HD + 1];
    __shared__ float ps[8][64];          // per-warp softmax probs

    const int b = blockIdx.x / NH;
    const int h = blockIdx.x % NH;
    const int tid = threadIdx.x;

    const float* base = d_qkv + (size_t)b * NTOK * QKVD + h * HD;

    for (int idx = tid; idx < 64 * HD; idx += 256) {
        int r = idx >> 5, d = idx & 31;
        if (r < NTOK) {
            qs[r][d] = base[r * QKVD + d] * SCALE;
            ks[r][d] = base[r * QKVD + DIM + d];
            vs[r][d] = base[r * QKVD + 2 * DIM + d];
        } else {
            ks[r][d] = 0.f;
            vs[r][d] = 0.f;
        }
    }
    __syncthreads();

    const int w    = tid >> 5;
    const int lane = tid & 31;
    const float* bptr = d_bias + h * NTOK * NTOK;
    const float* mptr = mask + (size_t)(b & (NWIN - 1)) * WIN * WIN;

    for (int row = w; row < NTOK; row += 8) {
        const int j0 = lane, j1 = lane + 32;
        const bool v1 = (j1 < NTOK);

        float s0 = 0.f, s1 = 0.f;
        #pragma unroll
        for (int d = 0; d < HD; d++) {
            float qd = qs[row][d];
            s0 += qd * ks[j0][d];
            s1 += qd * ks[j1][d];
        }
        s0 += bptr[row * NTOK + j0];
        s1 = v1 ? (s1 + bptr[row * NTOK + j1]) : -INFINITY;
        if (row >= NP) {
            if (j0 >= NP) s0 += mptr[(row - NP) * WIN + (j0 - NP)];
            if (v1)       s1 += mptr[(row - NP) * WIN + (j1 - NP)];
        }

        float mx = fmaxf(s0, s1);
        #pragma unroll
        for (int o = 16; o; o >>= 1) mx = fmaxf(mx, __shfl_xor_sync(0xffffffffu, mx, o));

        float e0 = expf(s0 - mx);
        float e1 = v1 ? expf(s1 - mx) : 0.f;
        float sm = e0 + e1;
        #pragma unroll
        for (int o = 16; o; o >>= 1) sm += __shfl_xor_sync(0xffffffffu, sm, o);
        float inv = 1.f / sm;

        ps[w][j0] = e0 * inv;
        ps[w][j1] = e1 * inv;
        __syncwarp();

        float o = 0.f;
        #pragma unroll
        for (int j = 0; j < NTOK; j++) o += ps[w][j] * vs[j][lane];

        d_att[((size_t)b * NTOK + row) * DIM + h * HD + lane] = o;
        __syncwarp();
    }
}

// ---------------- launch ----------------
extern "C" void kernel_launch(void* const* d_in, const int* in_sizes, int n_in,
                              void* d_out, int out_size)
{
    const float* x      = (const float*)d_in[0];
    const float* mask   = (const float*)d_in[1];
    const float* qkv_w  = (const float*)d_in[2];
    const float* qkv_b  = (const float*)d_in[3];
    const float* proj_w = (const float*)d_in[4];
    const float* proj_b = (const float*)d_in[5];
    const float* rpb    = (const float*)d_in[6];
    float* out          = (float*)d_out;

    // 1) relative-position bias (tiny)
    bias_kernel<<<(NH * NTOK * NTOK + 255) / 256, 256>>>(rpb);

    // 2) QKV GEMM: (55296 x 384) @ (1152 x 384)^T
    {
        dim3 grid(QKVD / 128, MTOK / 128);
        k_qkv<<<grid, 256>>>(x, qkv_w, qkv_b);
    }

    // 3) attention per (b, h)
    attn_kernel<<<B_ * NH, 256>>>(mask);

    // 4) projection GEMM: (55296 x 384) @ (384 x 384)^T -> out
    {
        dim3 grid(DIM / 128, MTOK / 128);
        k_proj<<<grid, 256>>>(proj_w, proj_b, out);
    }
}

// round 2
// speedup vs baseline: 2.3542x; 2.3542x over previous
#include <cuda_runtime.h>
#include <math.h>
#include <stdint.h>

// ---------------- problem constants ----------------
#define B_      1024
#define NTOK    54
#define WIN     49
#define NP      5
#define NH      12
#define HD      32
#define DIM     384
#define QKVD    1152
#define NWIN    64
#define WH      7
#define WW      7
#define SCALE   0.17677669529663687f
#define MTOK    (B_*NTOK)       // 55296

// ---------------- scratch ----------------
__device__ float d_qkv[(size_t)MTOK * QKVD];
__device__ float d_att[(size_t)MTOK * DIM];
__device__ float d_bias[NH * NTOK * NTOK];

// ---------------- bias precompute ----------------
__global__ void bias_kernel(const float* __restrict__ rpb) {
    int idx = blockIdx.x * blockDim.x + threadIdx.x;
    const int total = NH * NTOK * NTOK;
    if (idx >= total) return;
    int h  = idx / (NTOK * NTOK);
    int r  = idx % (NTOK * NTOK);
    int qi = r / NTOK, kj = r % NTOK;
    float v = 0.f;
    if (qi >= NP && kj >= NP) {
        int i = qi - NP, j = kj - NP;
        int ih = i / WW, iw = i % WW;
        int jh = j / WW, jw = j % WW;
        int rpi = (ih - jh + WH - 1) * (2 * WW - 1) + (iw - jw + WW - 1);
        v = rpb[rpi * NH + h];
    }
    d_bias[idx] = v;
}

// ================= tf32 tensor-core GEMM =================
// C[M,N] = A[M,K] @ W[N,K]^T + bias ;  M%128==0, N%128==0, K%16==0
#define BM 128
#define BN 128
#define BK 16
#define PAD_K 20                       // smem row stride (floats) -> conflict-free frags
#define ABYTES (BM * PAD_K * 4)        // 10240
#define BBYTES (BN * PAD_K * 4)

__device__ __forceinline__ uint32_t f2tf32(float f) {
    uint32_t r;
    asm("cvt.rna.tf32.f32 %0, %1;" : "=r"(r) : "f"(f));
    return r;
}

__device__ __forceinline__ void cp16(uint32_t smem, const float* g) {
    asm volatile("cp.async.cg.shared.global [%0], [%1], 16;\n" :: "r"(smem), "l"(g));
}

__device__ __forceinline__ void mma_tf32(float* c,
    uint32_t a0, uint32_t a1, uint32_t a2, uint32_t a3,
    uint32_t b0, uint32_t b1)
{
    asm volatile(
        "mma.sync.aligned.m16n8k8.row.col.f32.tf32.tf32.f32 "
        "{%0,%1,%2,%3}, {%4,%5,%6,%7}, {%8,%9}, {%0,%1,%2,%3};\n"
        : "+f"(c[0]), "+f"(c[1]), "+f"(c[2]), "+f"(c[3])
        : "r"(a0), "r"(a1), "r"(a2), "r"(a3), "r"(b0), "r"(b1));
}

template<int N>
__device__ __forceinline__ void tgemm_body(
    const float* __restrict__ A, const float* __restrict__ W,
    const float* __restrict__ bias, float* __restrict__ C, int K)
{
    __shared__ __align__(16) float As[2][BM * PAD_K];
    __shared__ __align__(16) float Bs[2][BN * PAD_K];

    const int tid  = threadIdx.x;
    const int warp = tid >> 5, lane = tid & 31;
    const int g    = lane >> 2, tg = lane & 3;
    const int wm   = warp & 1;        // warp m tile: 64 rows
    const int wn   = warp >> 1;       // warp n tile: 32 cols
    const int m0   = blockIdx.y * BM;
    const int n0   = blockIdx.x * BN;

    // cooperative load indexing: 256 threads, each does 2x16B for A and B
    const int lr = tid >> 2;          // 0..63
    const int lk = (tid & 3) * 4;     // 0,4,8,12
    const float* Ag = A + (size_t)(m0 + lr) * K + lk;
    const float* Wg = W + (size_t)(n0 + lr) * K + lk;

    uint32_t sA = (uint32_t)__cvta_generic_to_shared(&As[0][0]);
    uint32_t sB = (uint32_t)__cvta_generic_to_shared(&Bs[0][0]);
    const uint32_t sA0 = sA + (lr * PAD_K + lk) * 4;
    const uint32_t sA1 = sA + ((lr + 64) * PAD_K + lk) * 4;
    const uint32_t sB0 = sB + (lr * PAD_K + lk) * 4;
    const uint32_t sB1 = sB + ((lr + 64) * PAD_K + lk) * 4;

    float acc[4][4][4];
    #pragma unroll
    for (int i = 0; i < 4; i++)
        #pragma unroll
        for (int j = 0; j < 4; j++)
            #pragma unroll
            for (int c = 0; c < 4; c++) acc[i][j][c] = 0.f;

    const int nt = K / BK;

    // prologue: load tile 0 into buffer 0
    {
        cp16(sA0, Ag);  cp16(sA1, Ag + (size_t)64 * K);
        cp16(sB0, Wg);  cp16(sB1, Wg + (size_t)64 * K);
        asm volatile("cp.async.commit_group;\n");
    }

    for (int t = 0; t < nt; t++) {
        asm volatile("cp.async.wait_group 0;\n");
        __syncthreads();
        const int buf = t & 1;
        if (t + 1 < nt) {
            const float* ap = Ag + (size_t)(t + 1) * BK;
            const float* wp = Wg + (size_t)(t + 1) * BK;
            const uint32_t bo = (buf ^ 1) ? 1u : 0u;
            cp16(sA0 + bo * ABYTES, ap);
            cp16(sA1 + bo * ABYTES, ap + (size_t)64 * K);
            cp16(sB0 + bo * BBYTES, wp);
            cp16(sB1 + bo * BBYTES, wp + (size_t)64 * K);
            asm volatile("cp.async.commit_group;\n");
        }

        const float* __restrict__ Asb = As[buf];
        const float* __restrict__ Bsb = Bs[buf];

        #pragma unroll
        for (int s = 0; s < 2; s++) {
            const int kb = s * 8;
            uint32_t af[4][4], bfr[4][2];
            #pragma unroll
            for (int i = 0; i < 4; i++) {
                const int rb = wm * 64 + i * 16;
                af[i][0] = f2tf32(Asb[(rb + g)     * PAD_K + kb + tg]);
                af[i][1] = f2tf32(Asb[(rb + g + 8) * PAD_K + kb + tg]);
                af[i][2] = f2tf32(Asb[(rb + g)     * PAD_K + kb + tg + 4]);
                af[i][3] = f2tf32(Asb[(rb + g + 8) * PAD_K + kb + tg + 4]);
            }
            #pragma unroll
            for (int j = 0; j < 4; j++) {
                const int cb = wn * 32 + j * 8;
                bfr[j][0] = f2tf32(Bsb[(cb + g) * PAD_K + kb + tg]);
                bfr[j][1] = f2tf32(Bsb[(cb + g) * PAD_K + kb + tg + 4]);
            }
            #pragma unroll
            for (int i = 0; i < 4; i++)
                #pragma unroll
                for (int j = 0; j < 4; j++)
                    mma_tf32(acc[i][j], af[i][0], af[i][1], af[i][2], af[i][3],
                             bfr[j][0], bfr[j][1]);
        }
        __syncthreads();
    }

    // epilogue: add bias, store
    #pragma unroll
    for (int i = 0; i < 4; i++) {
        const int rb = m0 + wm * 64 + i * 16 + g;
        #pragma unroll
        for (int j = 0; j < 4; j++) {
            const int cb = n0 + wn * 32 + j * 8 + 2 * tg;
            const float b0v = bias[cb], b1v = bias[cb + 1];
            float2 v0, v1;
            v0.x = acc[i][j][0] + b0v;  v0.y = acc[i][j][1] + b1v;
            v1.x = acc[i][j][2] + b0v;  v1.y = acc[i][j][3] + b1v;
            *reinterpret_cast<float2*>(&C[(size_t)rb * N + cb])       = v0;
            *reinterpret_cast<float2*>(&C[(size_t)(rb + 8) * N + cb]) = v1;
        }
    }
}

__global__ __launch_bounds__(256, 2) void k_qkv(
    const float* __restrict__ x, const float* __restrict__ W,
    const float* __restrict__ b)
{
    tgemm_body<QKVD>(x, W, b, d_qkv, DIM);
}

__global__ __launch_bounds__(256, 2) void k_proj(
    const float* __restrict__ W, const float* __restrict__ b,
    float* __restrict__ out)
{
    tgemm_body<DIM>(d_att, W, b, out, DIM);
}

// ================= fused attention: one block per (b, h) =================
__global__ __launch_bounds__(256) void attn_kernel(const float* __restrict__ mask)
{
    __shared__ float qs[64][HD];         // q * SCALE, rows >= NTOK zeroed
    __shared__ float ks[64][HD + 1];
    __shared__ float vs[64][HD + 1];
    __shared__ float ps[8][2][64];       // per-warp probs for the row pair

    const int b = blockIdx.x / NH;
    const int h = blockIdx.x % NH;
    const int tid = threadIdx.x;

    const float* base = d_qkv + (size_t)b * NTOK * QKVD + h * HD;

    for (int idx = tid; idx < 64 * HD; idx += 256) {
        int r = idx >> 5, d = idx & 31;
        if (r < NTOK) {
            qs[r][d] = base[r * QKVD + d] * SCALE;
            ks[r][d] = base[r * QKVD + DIM + d];
            vs[r][d] = base[r * QKVD + 2 * DIM + d];
        } else {
            qs[r][d] = 0.f;
            ks[r][d] = 0.f;
            vs[r][d] = 0.f;
        }
    }
    __syncthreads();

    const int w    = tid >> 5;
    const int lane = tid & 31;
    const float* bptr = d_bias + h * NTOK * NTOK;
    const float* mptr = mask + (size_t)(b & (NWIN - 1)) * WIN * WIN;

    const int j0 = lane, j1 = lane + 32;
    const bool v1 = (j1 < NTOK);

    for (int r = w; r < NTOK; r += 16) {
        const bool has2 = (r + 8 < NTOK);
        const int r2 = has2 ? r + 8 : r;     // clamp -> all accesses valid

        float s0 = 0.f, s1 = 0.f, u0 = 0.f, u1 = 0.f;
        #pragma unroll
        for (int d = 0; d < HD; d++) {
            const float k0 = ks[j0][d];
            const float k1 = ks[j1][d];
            const float qa = qs[r][d];
            const float qb = qs[r2][d];
            s0 += qa * k0;  s1 += qa * k1;
            u0 += qb * k0;  u1 += qb * k1;
        }
        s0 += bptr[r * NTOK + j0];
        u0 += bptr[r2 * NTOK + j0];
        s1 = v1 ? (s1 + bptr[r * NTOK + j1])  : -INFINITY;
        u1 = v1 ? (u1 + bptr[r2 * NTOK + j1]) : -INFINITY;
        if (j0 >= NP) {
            if (r  >= NP) s0 += mptr[(r  - NP) * WIN + (j0 - NP)];
            if (r2 >= NP) u0 += mptr[(r2 - NP) * WIN + (j0 - NP)];
        }
        if (v1) {
            if (r  >= NP) s1 += mptr[(r  - NP) * WIN + (j1 - NP)];
            if (r2 >= NP) u1 += mptr[(r2 - NP) * WIN + (j1 - NP)];
        }

        // softmax row r
        float mx = fmaxf(s0, s1);
        #pragma unroll
        for (int o = 16; o; o >>= 1) mx = fmaxf(mx, __shfl_xor_sync(0xffffffffu, mx, o));
        float e0 = expf(s0 - mx);
        float e1 = v1 ? expf(s1 - mx) : 0.f;
        float sm = e0 + e1;
        #pragma unroll
        for (int o = 16; o; o >>= 1) sm += __shfl_xor_sync(0xffffffffu, sm, o);
        float inv = 1.f / sm;
        ps[w][0][j0] = e0 * inv;
        ps[w][0][j1] = e1 * inv;

        // softmax row r2
        float mx2 = fmaxf(u0, u1);
        #pragma unroll
        for (int o = 16; o; o >>= 1) mx2 = fmaxf(mx2, __shfl_xor_sync(0xffffffffu, mx2, o));
        float f0 = expf(u0 - mx2);
        float f1 = v1 ? expf(u1 - mx2) : 0.f;
        float sm2 = f0 + f1;
        #pragma unroll
        for (int o = 16; o; o >>= 1) sm2 += __shfl_xor_sync(0xffffffffu, sm2, o);
        float inv2 = 1.f / sm2;
        ps[w][1][j0] = f0 * inv2;
        ps[w][1][j1] = f1 * inv2;
        __syncwarp();

        // PV: both rows share the vs loads
        float o0 = 0.f, o1 = 0.f;
        #pragma unroll
        for (int j = 0; j < NTOK; j++) {
            const float vj = vs[j][lane];
            o0 += ps[w][0][j] * vj;
            o1 += ps[w][1][j] * vj;
        }

        d_att[((size_t)b * NTOK + r) * DIM + h * HD + lane] = o0;
        if (has2)
            d_att[((size_t)b * NTOK + r2) * DIM + h * HD + lane] = o1;
        __syncwarp();
    }
}

// ---------------- launch ----------------
extern "C" void kernel_launch(void* const* d_in, const int* in_sizes, int n_in,
                              void* d_out, int out_size)
{
    const float* x      = (const float*)d_in[0];
    const float* mask   = (const float*)d_in[1];
    const float* qkv_w  = (const float*)d_in[2];
    const float* qkv_b  = (const float*)d_in[3];
    const float* proj_w = (const float*)d_in[4];
    const float* proj_b = (const float*)d_in[5];
    const float* rpb    = (const float*)d_in[6];
    float* out          = (float*)d_out;

    bias_kernel<<<(NH * NTOK * NTOK + 255) / 256, 256>>>(rpb);

    {   // QKV: (55296 x 384) @ (1152 x 384)^T
        dim3 grid(QKVD / BN, MTOK / BM);
        k_qkv<<<grid, 256>>>(x, qkv_w, qkv_b);
    }

    attn_kernel<<<B_ * NH, 256>>>(mask);

    {   // proj: (55296 x 384) @ (384 x 384)^T
        dim3 grid(DIM / BN, MTOK / BM);
        k_proj<<<grid, 256>>>(proj_w, proj_b, out);
    }
}